// round 1
// baseline (speedup 1.0000x reference)
#include <cuda_runtime.h>

#define NN      100000
#define EE      1600000
#define INDIM   512
#define HID     64
#define NCLS    16

// ---------------- scratch (static device globals; no allocation) -------------
__device__ float g_deg[NN];
__device__ float g_dis[NN];
__device__ float g_selfnorm[NN];
__device__ float g_norm[EE];
__device__ float g_h1[(size_t)NN * HID];
__device__ float g_agg1[(size_t)NN * HID];
__device__ float g_h2[(size_t)NN * NCLS];
__device__ float g_agg2[(size_t)NN * NCLS];

// ---------------- normalization precompute ----------------------------------
__global__ void k_init_deg() {
    int i = blockIdx.x * blockDim.x + threadIdx.x;
    if (i < NN) g_deg[i] = 1.0f;   // self-loop weight
}

__global__ void k_deg_accum(const int* __restrict__ dst, const float* __restrict__ w) {
    int e = blockIdx.x * blockDim.x + threadIdx.x;
    if (e < EE) atomicAdd(&g_deg[dst[e]], w[e]);
}

__global__ void k_dis() {
    int i = blockIdx.x * blockDim.x + threadIdx.x;
    if (i < NN) {
        float d = g_deg[i];          // >= 1 always (self-loop)
        float r = rsqrtf(d);
        g_dis[i] = r;
        g_selfnorm[i] = r * r;       // dis[i] * 1.0 * dis[i]
    }
}

__global__ void k_norm(const int* __restrict__ src, const int* __restrict__ dst,
                       const float* __restrict__ w) {
    int e = blockIdx.x * blockDim.x + threadIdx.x;
    if (e < EE) g_norm[e] = g_dis[src[e]] * w[e] * g_dis[dst[e]];
}

// ---------------- GEMM1: h1 = x @ W1   (100000x512 @ 512x64) -----------------
// 128-row x 64-col tile per block, K-tiled by 32. 256 threads, 8x4 per thread.
__global__ void k_gemm1(const float* __restrict__ x, const float* __restrict__ W1) {
    __shared__ float xs[128][36];   // +4 pad (bank spread, keeps 16B align)
    __shared__ float ws[32][68];
    int tid = threadIdx.x;
    int tx = tid & 15;              // col group (tx*4 .. tx*4+3)
    int ty = tid >> 4;              // row group (ty*8 .. ty*8+7)
    int row0 = blockIdx.x * 128;

    float acc[8][4];
#pragma unroll
    for (int r = 0; r < 8; r++)
#pragma unroll
        for (int j = 0; j < 4; j++) acc[r][j] = 0.0f;

    for (int k0 = 0; k0 < INDIM; k0 += 32) {
        // load x tile: 128x32 = 1024 float4, 4 per thread (coalesced)
#pragma unroll
        for (int i = 0; i < 4; i++) {
            int idx = tid + i * 256;
            int r = idx >> 3;
            int c = (idx & 7) * 4;
            float4 v = make_float4(0.f, 0.f, 0.f, 0.f);
            int grow = row0 + r;
            if (grow < NN)
                v = *reinterpret_cast<const float4*>(&x[(size_t)grow * INDIM + k0 + c]);
            xs[r][c + 0] = v.x; xs[r][c + 1] = v.y; xs[r][c + 2] = v.z; xs[r][c + 3] = v.w;
        }
        // load W1 tile: 32x64 = 512 float4, 2 per thread
#pragma unroll
        for (int i = 0; i < 2; i++) {
            int idx = tid + i * 256;
            int kr = idx >> 4;
            int c = (idx & 15) * 4;
            float4 v = *reinterpret_cast<const float4*>(&W1[(size_t)(k0 + kr) * HID + c]);
            ws[kr][c + 0] = v.x; ws[kr][c + 1] = v.y; ws[kr][c + 2] = v.z; ws[kr][c + 3] = v.w;
        }
        __syncthreads();
#pragma unroll
        for (int kk = 0; kk < 32; kk++) {
            float b[4];
#pragma unroll
            for (int j = 0; j < 4; j++) b[j] = ws[kk][tx * 4 + j];
#pragma unroll
            for (int r = 0; r < 8; r++) {
                float a = xs[ty * 8 + r][kk];
#pragma unroll
                for (int j = 0; j < 4; j++) acc[r][j] = fmaf(a, b[j], acc[r][j]);
            }
        }
        __syncthreads();
    }
#pragma unroll
    for (int r = 0; r < 8; r++) {
        int grow = row0 + ty * 8 + r;
        if (grow < NN) {
            float4 v = make_float4(acc[r][0], acc[r][1], acc[r][2], acc[r][3]);
            *reinterpret_cast<float4*>(&g_h1[(size_t)grow * HID + tx * 4]) = v;
        }
    }
}

// ---------------- layer-1 aggregation ----------------------------------------
__global__ void k_selfloop1() {
    int idx = blockIdx.x * blockDim.x + threadIdx.x;
    if (idx < NN * HID) {
        int row = idx >> 6;
        g_agg1[idx] = g_h1[idx] * g_selfnorm[row];
    }
}

// one thread per (edge, 4-feature chunk): E*16 threads
__global__ void k_scatter1(const int* __restrict__ src, const int* __restrict__ dst) {
    long long idx = (long long)blockIdx.x * blockDim.x + threadIdx.x;
    if (idx >= (long long)EE * 16) return;
    int e = (int)(idx >> 4);
    int c = (int)(idx & 15) * 4;
    int s = src[e], d = dst[e];
    float nm = g_norm[e];
    float4 v = *reinterpret_cast<const float4*>(&g_h1[(size_t)s * HID + c]);
    float* o = &g_agg1[(size_t)d * HID + c];
    atomicAdd(o + 0, v.x * nm);
    atomicAdd(o + 1, v.y * nm);
    atomicAdd(o + 2, v.z * nm);
    atomicAdd(o + 3, v.w * nm);
}

// ---------------- GEMM2 (fused relu(agg1+b1) @ W2): 100000x64 @ 64x16 --------
__global__ void k_gemm2(const float* __restrict__ b1, const float* __restrict__ W2) {
    __shared__ float w2s[HID * NCLS];
    __shared__ float b1s[HID];
    int tid = threadIdx.x;
    for (int i = tid; i < HID * NCLS; i += blockDim.x) w2s[i] = W2[i];
    if (tid < HID) b1s[tid] = b1[tid];
    __syncthreads();
    int row = blockIdx.x * blockDim.x + tid;
    if (row >= NN) return;
    float acc[NCLS];
#pragma unroll
    for (int c = 0; c < NCLS; c++) acc[c] = 0.0f;
    const float* arow = &g_agg1[(size_t)row * HID];
#pragma unroll
    for (int k = 0; k < HID; k++) {
        float z = fmaxf(arow[k] + b1s[k], 0.0f);
#pragma unroll
        for (int c = 0; c < NCLS; c++) acc[c] = fmaf(z, w2s[k * NCLS + c], acc[c]);
    }
#pragma unroll
    for (int c = 0; c < NCLS; c++) g_h2[(size_t)row * NCLS + c] = acc[c];
}

// ---------------- layer-2 aggregation ----------------------------------------
__global__ void k_selfloop2() {
    int idx = blockIdx.x * blockDim.x + threadIdx.x;
    if (idx < NN * NCLS) {
        int row = idx >> 4;
        g_agg2[idx] = g_h2[idx] * g_selfnorm[row];
    }
}

// one thread per (edge, 4-feature chunk): E*4 threads
__global__ void k_scatter2(const int* __restrict__ src, const int* __restrict__ dst) {
    long long idx = (long long)blockIdx.x * blockDim.x + threadIdx.x;
    if (idx >= (long long)EE * 4) return;
    int e = (int)(idx >> 2);
    int c = (int)(idx & 3) * 4;
    int s = src[e], d = dst[e];
    float nm = g_norm[e];
    float4 v = *reinterpret_cast<const float4*>(&g_h2[(size_t)s * NCLS + c]);
    float* o = &g_agg2[(size_t)d * NCLS + c];
    atomicAdd(o + 0, v.x * nm);
    atomicAdd(o + 1, v.y * nm);
    atomicAdd(o + 2, v.z * nm);
    atomicAdd(o + 3, v.w * nm);
}

// ---------------- bias + log_softmax ------------------------------------------
__global__ void k_softmax(const float* __restrict__ b2, float* __restrict__ out) {
    __shared__ float b2s[NCLS];
    if (threadIdx.x < NCLS) b2s[threadIdx.x] = b2[threadIdx.x];
    __syncthreads();
    int row = blockIdx.x * blockDim.x + threadIdx.x;
    if (row >= NN) return;
    float v[NCLS];
    float m = -1e30f;
#pragma unroll
    for (int c = 0; c < NCLS; c++) {
        v[c] = g_agg2[(size_t)row * NCLS + c] + b2s[c];
        m = fmaxf(m, v[c]);
    }
    float s = 0.0f;
#pragma unroll
    for (int c = 0; c < NCLS; c++) s += expf(v[c] - m);
    float ls = logf(s) + m;
#pragma unroll
    for (int c = 0; c < NCLS; c++) out[(size_t)row * NCLS + c] = v[c] - ls;
}

// ---------------- launch ------------------------------------------------------
extern "C" void kernel_launch(void* const* d_in, const int* in_sizes, int n_in,
                              void* d_out, int out_size) {
    const float* x  = (const float*)d_in[0];
    const int*   ei = (const int*)  d_in[1];
    const float* ew = (const float*)d_in[2];
    const float* W1 = (const float*)d_in[3];
    const float* b1 = (const float*)d_in[4];
    const float* W2 = (const float*)d_in[5];
    const float* b2 = (const float*)d_in[6];
    float* out = (float*)d_out;

    const int* src = ei;        // edge_index[0]
    const int* dst = ei + EE;   // edge_index[1]

    k_init_deg <<<(NN + 255) / 256, 256>>>();
    k_deg_accum<<<(EE + 255) / 256, 256>>>(dst, ew);
    k_dis      <<<(NN + 255) / 256, 256>>>();
    k_norm     <<<(EE + 255) / 256, 256>>>(src, dst, ew);

    k_gemm1    <<<(NN + 127) / 128, 256>>>(x, W1);
    k_selfloop1<<<(NN * HID + 255) / 256, 256>>>();
    k_scatter1 <<<(int)(((long long)EE * 16 + 255) / 256), 256>>>(src, dst);

    k_gemm2    <<<(NN + 255) / 256, 256>>>(b1, W2);
    k_selfloop2<<<(NN * NCLS + 255) / 256, 256>>>();
    k_scatter2 <<<(int)(((long long)EE * 4 + 255) / 256), 256>>>(src, dst);

    k_softmax  <<<(NN + 255) / 256, 256>>>(b2, out);
}

// round 2
// speedup vs baseline: 1.3769x; 1.3769x over previous
#include <cuda_runtime.h>

#define NN      100000
#define EE      1600000
#define INDIM   512
#define HID     64
#define NCLS    16

typedef unsigned long long ull;

// ---------------- scratch (static device globals; no allocation) -------------
__device__ float g_deg[NN];
__device__ float g_dis[NN];
__device__ float g_selfnorm[NN];
__device__ float g_norm[EE];
__device__ float g_h1[(size_t)NN * HID];
__device__ float g_agg1[(size_t)NN * HID];
__device__ float g_h2[(size_t)NN * NCLS];
__device__ float g_agg2[(size_t)NN * NCLS];

// ---------------- packed f32x2 helpers ---------------------------------------
__device__ __forceinline__ ull ffma2(ull a, ull b, ull c) {
    ull d;
    asm("fma.rn.f32x2 %0, %1, %2, %3;" : "=l"(d) : "l"(a), "l"(b), "l"(c));
    return d;
}
__device__ __forceinline__ void unpack2(ull v, float& lo, float& hi) {
    asm("mov.b64 {%0, %1}, %2;" : "=f"(lo), "=f"(hi) : "l"(v));
}

__device__ __forceinline__ void red_v4(float* p, float a, float b, float c, float d) {
    asm volatile("red.global.add.v4.f32 [%0], {%1, %2, %3, %4};"
                 :: "l"(p), "f"(a), "f"(b), "f"(c), "f"(d) : "memory");
}

// ---------------- normalization precompute ----------------------------------
__global__ void k_init_deg() {
    int i = blockIdx.x * blockDim.x + threadIdx.x;
    if (i < NN) g_deg[i] = 1.0f;   // self-loop weight
}

__global__ void k_deg_accum(const int* __restrict__ dst, const float* __restrict__ w) {
    int e = blockIdx.x * blockDim.x + threadIdx.x;
    if (e < EE) atomicAdd(&g_deg[dst[e]], w[e]);
}

__global__ void k_dis() {
    int i = blockIdx.x * blockDim.x + threadIdx.x;
    if (i < NN) {
        float d = g_deg[i];          // >= 1 always (self-loop)
        float r = rsqrtf(d);
        g_dis[i] = r;
        g_selfnorm[i] = r * r;
    }
}

// 2 edges per thread for memory-level parallelism on the dis[] gathers
__global__ void k_norm(const int* __restrict__ src, const int* __restrict__ dst,
                       const float* __restrict__ w) {
    int t = blockIdx.x * blockDim.x + threadIdx.x;
    int e0 = t * 2;
    if (e0 + 1 < EE) {
        int s0 = src[e0], s1 = src[e0 + 1];
        int d0 = dst[e0], d1 = dst[e0 + 1];
        float w0 = w[e0], w1 = w[e0 + 1];
        float a0 = g_dis[s0], a1 = g_dis[s1];
        float b0 = g_dis[d0], b1 = g_dis[d1];
        g_norm[e0]     = a0 * w0 * b0;
        g_norm[e0 + 1] = a1 * w1 * b1;
    } else if (e0 < EE) {
        g_norm[e0] = g_dis[src[e0]] * w[e0] * g_dis[dst[e0]];
    }
}

// ---------------- GEMM1: h1 = x @ W1 (100000x512 @ 512x64), packed f32x2 -----
// 128-row x 64-col tile, K-tiled by 32. 256 threads.
// Thread computes 4 row-pairs x 4 cols (cols tx, tx+16, tx+32, tx+48).
// xs_t : transposed x tile  -> row-pair operand is one LDS.64
// ws2  : duplicated W tile (w,w) -> b operand is one LDS.64, conflict-free
__global__ void k_gemm1(const float* __restrict__ x, const float* __restrict__ W1) {
    __shared__ float xs_t[32][134];      // [kk][row], pad->even stride, 8B align
    __shared__ float ws2[32][2 * HID];   // [kk][2*col] duplicated pairs
    int tid = threadIdx.x;
    int tx = tid & 15;                   // col base
    int ty = tid >> 4;                   // row-group (8 rows)
    int row0 = blockIdx.x * 128;

    ull acc[4][4];
#pragma unroll
    for (int p = 0; p < 4; p++)
#pragma unroll
        for (int j = 0; j < 4; j++) acc[p][j] = 0ull;

    for (int k0 = 0; k0 < INDIM; k0 += 32) {
        // x tile 128x32 -> transposed store (scalar STS)
#pragma unroll
        for (int i = 0; i < 4; i++) {
            int idx = tid + i * 256;
            int r = idx >> 3;
            int cb = (idx & 7) * 4;
            float4 v = make_float4(0.f, 0.f, 0.f, 0.f);
            int grow = row0 + r;
            if (grow < NN)
                v = *reinterpret_cast<const float4*>(&x[(size_t)grow * INDIM + k0 + cb]);
            xs_t[cb + 0][r] = v.x;
            xs_t[cb + 1][r] = v.y;
            xs_t[cb + 2][r] = v.z;
            xs_t[cb + 3][r] = v.w;
        }
        // W tile 32x64 -> duplicated-pair store
#pragma unroll
        for (int i = 0; i < 2; i++) {
            int idx = tid + i * 256;
            int kr = idx >> 4;
            int c = (idx & 15) * 4;
            float4 v = *reinterpret_cast<const float4*>(&W1[(size_t)(k0 + kr) * HID + c]);
            *reinterpret_cast<float2*>(&ws2[kr][2 * (c + 0)]) = make_float2(v.x, v.x);
            *reinterpret_cast<float2*>(&ws2[kr][2 * (c + 1)]) = make_float2(v.y, v.y);
            *reinterpret_cast<float2*>(&ws2[kr][2 * (c + 2)]) = make_float2(v.z, v.z);
            *reinterpret_cast<float2*>(&ws2[kr][2 * (c + 3)]) = make_float2(v.w, v.w);
        }
        __syncthreads();
#pragma unroll
        for (int kk = 0; kk < 32; kk++) {
            ull b[4], a[4];
#pragma unroll
            for (int j = 0; j < 4; j++)
                b[j] = *reinterpret_cast<const ull*>(&ws2[kk][2 * (tx + 16 * j)]);
#pragma unroll
            for (int p = 0; p < 4; p++)
                a[p] = *reinterpret_cast<const ull*>(&xs_t[kk][ty * 8 + 2 * p]);
#pragma unroll
            for (int p = 0; p < 4; p++)
#pragma unroll
                for (int j = 0; j < 4; j++)
                    acc[p][j] = ffma2(a[p], b[j], acc[p][j]);
        }
        __syncthreads();
    }
    // epilogue: write h1 and agg1 = h1 * selfnorm (fused self-loop)
#pragma unroll
    for (int p = 0; p < 4; p++) {
        int rlo = row0 + ty * 8 + 2 * p;
        int rhi = rlo + 1;
        float sl = (rlo < NN) ? g_selfnorm[rlo] : 0.f;
        float sh = (rhi < NN) ? g_selfnorm[rhi] : 0.f;
#pragma unroll
        for (int j = 0; j < 4; j++) {
            float lo, hi;
            unpack2(acc[p][j], lo, hi);
            int col = tx + 16 * j;
            if (rlo < NN) {
                g_h1[(size_t)rlo * HID + col] = lo;
                g_agg1[(size_t)rlo * HID + col] = lo * sl;
            }
            if (rhi < NN) {
                g_h1[(size_t)rhi * HID + col] = hi;
                g_agg1[(size_t)rhi * HID + col] = hi * sh;
            }
        }
    }
}

// ---------------- layer-1 scatter: vector RED --------------------------------
// 16 threads per edge, each does one float4 -> one red.global.add.v4.f32
__global__ void k_scatter1(const int* __restrict__ src, const int* __restrict__ dst) {
    long long idx = (long long)blockIdx.x * blockDim.x + threadIdx.x;
    if (idx >= (long long)EE * 16) return;
    int e = (int)(idx >> 4);
    int c = (int)(idx & 15) * 4;
    int s = src[e], d = dst[e];
    float nm = g_norm[e];
    float4 v = *reinterpret_cast<const float4*>(&g_h1[(size_t)s * HID + c]);
    red_v4(&g_agg1[(size_t)d * HID + c], v.x * nm, v.y * nm, v.z * nm, v.w * nm);
}

// ---------------- GEMM2 fused: relu(agg1+b1) @ W2, + self-loop epilogue ------
__global__ void k_gemm2(const float* __restrict__ b1, const float* __restrict__ W2) {
    __shared__ float w2s[HID * NCLS];
    __shared__ float b1s[HID];
    int tid = threadIdx.x;
    for (int i = tid; i < HID * NCLS; i += blockDim.x) w2s[i] = W2[i];
    if (tid < HID) b1s[tid] = b1[tid];
    __syncthreads();
    int row = blockIdx.x * blockDim.x + tid;
    if (row >= NN) return;
    float acc[NCLS];
#pragma unroll
    for (int c = 0; c < NCLS; c++) acc[c] = 0.0f;
    const float4* arow = reinterpret_cast<const float4*>(&g_agg1[(size_t)row * HID]);
#pragma unroll
    for (int k4 = 0; k4 < HID / 4; k4++) {
        float4 v = arow[k4];
        float z0 = fmaxf(v.x + b1s[4 * k4 + 0], 0.0f);
        float z1 = fmaxf(v.y + b1s[4 * k4 + 1], 0.0f);
        float z2 = fmaxf(v.z + b1s[4 * k4 + 2], 0.0f);
        float z3 = fmaxf(v.w + b1s[4 * k4 + 3], 0.0f);
#pragma unroll
        for (int c = 0; c < NCLS; c++) {
            acc[c] = fmaf(z0, w2s[(4 * k4 + 0) * NCLS + c], acc[c]);
            acc[c] = fmaf(z1, w2s[(4 * k4 + 1) * NCLS + c], acc[c]);
            acc[c] = fmaf(z2, w2s[(4 * k4 + 2) * NCLS + c], acc[c]);
            acc[c] = fmaf(z3, w2s[(4 * k4 + 3) * NCLS + c], acc[c]);
        }
    }
    float sl = g_selfnorm[row];
#pragma unroll
    for (int c = 0; c < NCLS; c++) {
        g_h2[(size_t)row * NCLS + c] = acc[c];
        g_agg2[(size_t)row * NCLS + c] = acc[c] * sl;   // fused self-loop
    }
}

// ---------------- layer-2 scatter: vector RED --------------------------------
__global__ void k_scatter2(const int* __restrict__ src, const int* __restrict__ dst) {
    long long idx = (long long)blockIdx.x * blockDim.x + threadIdx.x;
    if (idx >= (long long)EE * 4) return;
    int e = (int)(idx >> 2);
    int c = (int)(idx & 3) * 4;
    int s = src[e], d = dst[e];
    float nm = g_norm[e];
    float4 v = *reinterpret_cast<const float4*>(&g_h2[(size_t)s * NCLS + c]);
    red_v4(&g_agg2[(size_t)d * NCLS + c], v.x * nm, v.y * nm, v.z * nm, v.w * nm);
}

// ---------------- bias + log_softmax -----------------------------------------
__global__ void k_softmax(const float* __restrict__ b2, float* __restrict__ out) {
    __shared__ float b2s[NCLS];
    if (threadIdx.x < NCLS) b2s[threadIdx.x] = b2[threadIdx.x];
    __syncthreads();
    int row = blockIdx.x * blockDim.x + threadIdx.x;
    if (row >= NN) return;
    float v[NCLS];
    float m = -1e30f;
#pragma unroll
    for (int c = 0; c < NCLS; c++) {
        v[c] = g_agg2[(size_t)row * NCLS + c] + b2s[c];
        m = fmaxf(m, v[c]);
    }
    float s = 0.0f;
#pragma unroll
    for (int c = 0; c < NCLS; c++) s += expf(v[c] - m);
    float ls = logf(s) + m;
#pragma unroll
    for (int c = 0; c < NCLS; c++) out[(size_t)row * NCLS + c] = v[c] - ls;
}

// ---------------- launch ------------------------------------------------------
extern "C" void kernel_launch(void* const* d_in, const int* in_sizes, int n_in,
                              void* d_out, int out_size) {
    const float* x  = (const float*)d_in[0];
    const int*   ei = (const int*)  d_in[1];
    const float* ew = (const float*)d_in[2];
    const float* W1 = (const float*)d_in[3];
    const float* b1 = (const float*)d_in[4];
    const float* W2 = (const float*)d_in[5];
    const float* b2 = (const float*)d_in[6];
    float* out = (float*)d_out;

    const int* src = ei;        // edge_index[0]
    const int* dst = ei + EE;   // edge_index[1]

    k_init_deg <<<(NN + 255) / 256, 256>>>();
    k_deg_accum<<<(EE + 255) / 256, 256>>>(dst, ew);
    k_dis      <<<(NN + 255) / 256, 256>>>();
    k_norm     <<<(EE / 2 + 255) / 256, 256>>>(src, dst, ew);

    k_gemm1    <<<(NN + 127) / 128, 256>>>(x, W1);
    k_scatter1 <<<(int)(((long long)EE * 16 + 255) / 256), 256>>>(src, dst);

    k_gemm2    <<<(NN + 255) / 256, 256>>>(b1, W2);
    k_scatter2 <<<(int)(((long long)EE * 4 + 255) / 256), 256>>>(src, dst);

    k_softmax  <<<(NN + 255) / 256, 256>>>(b2, out);
}

// round 4
// speedup vs baseline: 1.5764x; 1.1449x over previous
#include <cuda_runtime.h>
#include <cuda_bf16.h>
#include <cstdint>

#define NN      100000
#define EE      1600000
#define INDIM   512
#define HID     64
#define NCLS    16

typedef unsigned long long ull;

// ---------------- scratch (static device globals; no allocation) -------------
__device__ float g_deg[NN];
__device__ float g_dis[NN];
__device__ float g_selfnorm[NN];
__device__ float g_norm[EE];
__device__ float g_h1[(size_t)NN * HID];
__device__ float g_agg1[(size_t)NN * HID];
__device__ float g_h2[(size_t)NN * NCLS];
__device__ float g_agg2[(size_t)NN * NCLS];
// W1^T split into bf16 hi/lo, layout [HID][INDIM] (N-major rows, K contiguous)
__device__ __nv_bfloat16 g_w1t_hi[HID * INDIM];
__device__ __nv_bfloat16 g_w1t_lo[HID * INDIM];

// ---------------- helpers -----------------------------------------------------
__device__ __forceinline__ void red_v4(float* p, float a, float b, float c, float d) {
    asm volatile("red.global.add.v4.f32 [%0], {%1, %2, %3, %4};"
                 :: "l"(p), "f"(a), "f"(b), "f"(c), "f"(d) : "memory");
}

// pack two f32 -> bf16x2 ('first' in the low half)
__device__ __forceinline__ uint32_t packbf(float first, float second) {
    uint32_t r;
    asm("cvt.rn.bf16x2.f32 %0, %1, %2;" : "=r"(r) : "f"(second), "f"(first));
    return r;
}

__device__ __forceinline__ void mma_bf16(float& d0, float& d1, float& d2, float& d3,
                                         uint32_t a0, uint32_t a1, uint32_t a2, uint32_t a3,
                                         uint32_t b0, uint32_t b1) {
    asm volatile(
        "mma.sync.aligned.m16n8k16.row.col.f32.bf16.bf16.f32 "
        "{%0,%1,%2,%3}, {%4,%5,%6,%7}, {%8,%9}, {%0,%1,%2,%3};"
        : "+f"(d0), "+f"(d1), "+f"(d2), "+f"(d3)
        : "r"(a0), "r"(a1), "r"(a2), "r"(a3), "r"(b0), "r"(b1));
}

// ---------------- normalization precompute ----------------------------------
__global__ void k_init_deg() {
    int i = blockIdx.x * blockDim.x + threadIdx.x;
    if (i < NN) g_deg[i] = 1.0f;
}

__global__ void k_deg_accum(const int* __restrict__ dst, const float* __restrict__ w) {
    int e = blockIdx.x * blockDim.x + threadIdx.x;
    if (e < EE) atomicAdd(&g_deg[dst[e]], w[e]);
}

__global__ void k_dis() {
    int i = blockIdx.x * blockDim.x + threadIdx.x;
    if (i < NN) {
        float d = g_deg[i];
        float r = rsqrtf(d);
        g_dis[i] = r;
        g_selfnorm[i] = r * r;
    }
}

__global__ void k_norm(const int* __restrict__ src, const int* __restrict__ dst,
                       const float* __restrict__ w) {
    int t = blockIdx.x * blockDim.x + threadIdx.x;
    int e0 = t * 2;
    if (e0 + 1 < EE) {
        int s0 = src[e0], s1 = src[e0 + 1];
        int d0 = dst[e0], d1 = dst[e0 + 1];
        float w0 = w[e0], w1 = w[e0 + 1];
        float a0 = g_dis[s0], a1 = g_dis[s1];
        float b0 = g_dis[d0], b1 = g_dis[d1];
        g_norm[e0]     = a0 * w0 * b0;
        g_norm[e0 + 1] = a1 * w1 * b1;
    } else if (e0 < EE) {
        g_norm[e0] = g_dis[src[e0]] * w[e0] * g_dis[dst[e0]];
    }
}

// ---------------- W1^T split prep --------------------------------------------
__global__ void k_prep_w(const float* __restrict__ W1) {
    int idx = blockIdx.x * blockDim.x + threadIdx.x;
    if (idx >= HID * INDIM) return;
    int n = idx >> 9;          // /512
    int k = idx & 511;
    float w = W1[k * HID + n];
    __nv_bfloat16 h = __float2bfloat16_rn(w);
    float hf = __bfloat162float(h);
    g_w1t_hi[n * INDIM + k] = h;
    g_w1t_lo[n * INDIM + k] = __float2bfloat16_rn(w - hf);
}

// ---------------- GEMM1 via mma.sync split-bf16 -------------------------------
// Block: 256 thr (8 warps), M-tile 128, N=64, K-chunk 32 (2 k16-steps).
// Warp w computes rows [w*16, w*16+16) x all 64 cols (8 n-tiles of m16n8).
// smem tiles bf16 with pitch 40 elems (80B): bank map (20r+q)%32 is a permutation
// over the fragment-read lanes -> conflict-free LDS.32.
#define KC     32
#define APITCH 40                    // bf16 elements
#define APB    (APITCH * 2)          // 80 bytes

__global__ void __launch_bounds__(256)
k_gemm1_tc(const float* __restrict__ x) {
    __shared__ uint8_t As_hi[128 * APB];
    __shared__ uint8_t As_lo[128 * APB];
    __shared__ uint8_t Bs_hi[64 * APB];
    __shared__ uint8_t Bs_lo[64 * APB];

    int tid = threadIdx.x;
    int wid = tid >> 5;
    int lane = tid & 31;
    int lt = lane >> 2;              // 0..7
    int q  = lane & 3;               // 0..3
    int row0 = blockIdx.x * 128;

    float acc[8][4];
#pragma unroll
    for (int t = 0; t < 8; t++)
#pragma unroll
        for (int j = 0; j < 4; j++) acc[t][j] = 0.0f;

    const uint2* whi = reinterpret_cast<const uint2*>(g_w1t_hi);
    const uint2* wlo = reinterpret_cast<const uint2*>(g_w1t_lo);

    for (int k0 = 0; k0 < INDIM; k0 += KC) {
        // ---- A tile: 128x32 fp32 -> split bf16 hi/lo (1024 float4, 4/thread)
#pragma unroll
        for (int i = 0; i < 4; i++) {
            int idx = tid + i * 256;
            int r = idx >> 3;
            int c4 = (idx & 7) * 4;
            float4 v = make_float4(0.f, 0.f, 0.f, 0.f);
            int grow = row0 + r;
            if (grow < NN)
                v = *reinterpret_cast<const float4*>(&x[(size_t)grow * INDIM + k0 + c4]);
            uint32_t hp0 = packbf(v.x, v.y);
            uint32_t hp1 = packbf(v.z, v.w);
            float hx = __uint_as_float(hp0 << 16);
            float hy = __uint_as_float(hp0 & 0xFFFF0000u);
            float hz = __uint_as_float(hp1 << 16);
            float hw = __uint_as_float(hp1 & 0xFFFF0000u);
            uint32_t lp0 = packbf(v.x - hx, v.y - hy);
            uint32_t lp1 = packbf(v.z - hz, v.w - hw);
            uint32_t off = (uint32_t)(r * APB + c4 * 2);
            *reinterpret_cast<uint2*>(As_hi + off) = make_uint2(hp0, hp1);
            *reinterpret_cast<uint2*>(As_lo + off) = make_uint2(lp0, lp1);
        }
        // ---- B tiles: 64x32 bf16 hi/lo (512 uint2 each, 2/thread)
#pragma unroll
        for (int i = 0; i < 2; i++) {
            int idx = tid + i * 256;
            int n = idx >> 3;
            int j = idx & 7;                       // uint2 col (4 bf16 each)
            int gidx = n * 128 + (k0 >> 2) + j;
            uint32_t off = (uint32_t)(n * APB + j * 8);
            *reinterpret_cast<uint2*>(Bs_hi + off) = whi[gidx];
            *reinterpret_cast<uint2*>(Bs_lo + off) = wlo[gidx];
        }
        __syncthreads();

#pragma unroll
        for (int ks = 0; ks < 2; ks++) {
            uint32_t abase = (uint32_t)((wid * 16 + lt) * APB + ks * 32 + q * 4);
            uint32_t ah0 = *reinterpret_cast<const uint32_t*>(As_hi + abase);
            uint32_t ah1 = *reinterpret_cast<const uint32_t*>(As_hi + abase + 8 * APB);
            uint32_t ah2 = *reinterpret_cast<const uint32_t*>(As_hi + abase + 16);
            uint32_t ah3 = *reinterpret_cast<const uint32_t*>(As_hi + abase + 8 * APB + 16);
            uint32_t al0 = *reinterpret_cast<const uint32_t*>(As_lo + abase);
            uint32_t al1 = *reinterpret_cast<const uint32_t*>(As_lo + abase + 8 * APB);
            uint32_t al2 = *reinterpret_cast<const uint32_t*>(As_lo + abase + 16);
            uint32_t al3 = *reinterpret_cast<const uint32_t*>(As_lo + abase + 8 * APB + 16);
#pragma unroll
            for (int nt = 0; nt < 8; nt++) {
                uint32_t bbase = (uint32_t)((nt * 8 + lt) * APB + ks * 32 + q * 4);
                uint32_t bh0 = *reinterpret_cast<const uint32_t*>(Bs_hi + bbase);
                uint32_t bh1 = *reinterpret_cast<const uint32_t*>(Bs_hi + bbase + 16);
                uint32_t bl0 = *reinterpret_cast<const uint32_t*>(Bs_lo + bbase);
                uint32_t bl1 = *reinterpret_cast<const uint32_t*>(Bs_lo + bbase + 16);
                mma_bf16(acc[nt][0], acc[nt][1], acc[nt][2], acc[nt][3],
                         ah0, ah1, ah2, ah3, bh0, bh1);
                mma_bf16(acc[nt][0], acc[nt][1], acc[nt][2], acc[nt][3],
                         ah0, ah1, ah2, ah3, bl0, bl1);
                mma_bf16(acc[nt][0], acc[nt][1], acc[nt][2], acc[nt][3],
                         al0, al1, al2, al3, bh0, bh1);
            }
        }
        __syncthreads();
    }

    // ---- epilogue: write h1 and agg1 = h1 * selfnorm
    int rA = row0 + wid * 16 + lt;
    int rB = rA + 8;
    float slA = (rA < NN) ? g_selfnorm[rA] : 0.f;
    float slB = (rB < NN) ? g_selfnorm[rB] : 0.f;
#pragma unroll
    for (int nt = 0; nt < 8; nt++) {
        int col = nt * 8 + q * 2;
        if (rA < NN) {
            *reinterpret_cast<float2*>(&g_h1[(size_t)rA * HID + col]) =
                make_float2(acc[nt][0], acc[nt][1]);
            *reinterpret_cast<float2*>(&g_agg1[(size_t)rA * HID + col]) =
                make_float2(acc[nt][0] * slA, acc[nt][1] * slA);
        }
        if (rB < NN) {
            *reinterpret_cast<float2*>(&g_h1[(size_t)rB * HID + col]) =
                make_float2(acc[nt][2], acc[nt][3]);
            *reinterpret_cast<float2*>(&g_agg1[(size_t)rB * HID + col]) =
                make_float2(acc[nt][2] * slB, acc[nt][3] * slB);
        }
    }
}

// ---------------- layer-1 scatter: vector RED --------------------------------
__global__ void k_scatter1(const int* __restrict__ src, const int* __restrict__ dst) {
    long long idx = (long long)blockIdx.x * blockDim.x + threadIdx.x;
    if (idx >= (long long)EE * 16) return;
    int e = (int)(idx >> 4);
    int c = (int)(idx & 15) * 4;
    int s = src[e], d = dst[e];
    float nm = g_norm[e];
    float4 v = *reinterpret_cast<const float4*>(&g_h1[(size_t)s * HID + c]);
    red_v4(&g_agg1[(size_t)d * HID + c], v.x * nm, v.y * nm, v.z * nm, v.w * nm);
}

// ---------------- GEMM2 fused: relu(agg1+b1) @ W2, + self-loop ----------------
__global__ void k_gemm2(const float* __restrict__ b1, const float* __restrict__ W2) {
    __shared__ float w2s[HID * NCLS];
    __shared__ float b1s[HID];
    int tid = threadIdx.x;
    for (int i = tid; i < HID * NCLS; i += blockDim.x) w2s[i] = W2[i];
    if (tid < HID) b1s[tid] = b1[tid];
    __syncthreads();
    int row = blockIdx.x * blockDim.x + tid;
    if (row >= NN) return;
    float acc[NCLS];
#pragma unroll
    for (int c = 0; c < NCLS; c++) acc[c] = 0.0f;
    const float4* arow = reinterpret_cast<const float4*>(&g_agg1[(size_t)row * HID]);
#pragma unroll
    for (int k4 = 0; k4 < HID / 4; k4++) {
        float4 v = arow[k4];
        float z0 = fmaxf(v.x + b1s[4 * k4 + 0], 0.0f);
        float z1 = fmaxf(v.y + b1s[4 * k4 + 1], 0.0f);
        float z2 = fmaxf(v.z + b1s[4 * k4 + 2], 0.0f);
        float z3 = fmaxf(v.w + b1s[4 * k4 + 3], 0.0f);
#pragma unroll
        for (int c = 0; c < NCLS; c++) {
            acc[c] = fmaf(z0, w2s[(4 * k4 + 0) * NCLS + c], acc[c]);
            acc[c] = fmaf(z1, w2s[(4 * k4 + 1) * NCLS + c], acc[c]);
            acc[c] = fmaf(z2, w2s[(4 * k4 + 2) * NCLS + c], acc[c]);
            acc[c] = fmaf(z3, w2s[(4 * k4 + 3) * NCLS + c], acc[c]);
        }
    }
    float sl = g_selfnorm[row];
#pragma unroll
    for (int c = 0; c < NCLS; c++) {
        g_h2[(size_t)row * NCLS + c] = acc[c];
        g_agg2[(size_t)row * NCLS + c] = acc[c] * sl;
    }
}

// ---------------- layer-2 scatter ---------------------------------------------
__global__ void k_scatter2(const int* __restrict__ src, const int* __restrict__ dst) {
    long long idx = (long long)blockIdx.x * blockDim.x + threadIdx.x;
    if (idx >= (long long)EE * 4) return;
    int e = (int)(idx >> 2);
    int c = (int)(idx & 3) * 4;
    int s = src[e], d = dst[e];
    float nm = g_norm[e];
    float4 v = *reinterpret_cast<const float4*>(&g_h2[(size_t)s * NCLS + c]);
    red_v4(&g_agg2[(size_t)d * NCLS + c], v.x * nm, v.y * nm, v.z * nm, v.w * nm);
}

// ---------------- bias + log_softmax ------------------------------------------
__global__ void k_softmax(const float* __restrict__ b2, float* __restrict__ out) {
    __shared__ float b2s[NCLS];
    if (threadIdx.x < NCLS) b2s[threadIdx.x] = b2[threadIdx.x];
    __syncthreads();
    int row = blockIdx.x * blockDim.x + threadIdx.x;
    if (row >= NN) return;
    float v[NCLS];
    float m = -1e30f;
#pragma unroll
    for (int c = 0; c < NCLS; c++) {
        v[c] = g_agg2[(size_t)row * NCLS + c] + b2s[c];
        m = fmaxf(m, v[c]);
    }
    float s = 0.0f;
#pragma unroll
    for (int c = 0; c < NCLS; c++) s += expf(v[c] - m);
    float ls = logf(s) + m;
#pragma unroll
    for (int c = 0; c < NCLS; c++) out[(size_t)row * NCLS + c] = v[c] - ls;
}

// ---------------- launch ------------------------------------------------------
extern "C" void kernel_launch(void* const* d_in, const int* in_sizes, int n_in,
                              void* d_out, int out_size) {
    const float* x  = (const float*)d_in[0];
    const int*   ei = (const int*)  d_in[1];
    const float* ew = (const float*)d_in[2];
    const float* W1 = (const float*)d_in[3];
    const float* b1 = (const float*)d_in[4];
    const float* W2 = (const float*)d_in[5];
    const float* b2 = (const float*)d_in[6];
    float* out = (float*)d_out;

    const int* src = ei;
    const int* dst = ei + EE;

    k_init_deg <<<(NN + 255) / 256, 256>>>();
    k_deg_accum<<<(EE + 255) / 256, 256>>>(dst, ew);
    k_dis      <<<(NN + 255) / 256, 256>>>();
    k_norm     <<<(EE / 2 + 255) / 256, 256>>>(src, dst, ew);
    k_prep_w   <<<(HID * INDIM + 255) / 256, 256>>>(W1);

    k_gemm1_tc <<<(NN + 127) / 128, 256>>>(x);
    k_scatter1 <<<(int)(((long long)EE * 16 + 255) / 256), 256>>>(src, dst);

    k_gemm2    <<<(NN + 255) / 256, 256>>>(b1, W2);
    k_scatter2 <<<(int)(((long long)EE * 4 + 255) / 256), 256>>>(src, dst);

    k_softmax  <<<(NN + 255) / 256, 256>>>(b2, out);
}

// round 5
// speedup vs baseline: 1.8330x; 1.1627x over previous
#include <cuda_runtime.h>
#include <cuda_bf16.h>
#include <cstdint>

#define NN      100000
#define EE      1600000
#define INDIM   512
#define HID     64
#define NCLS    16
#define NCH     ((NN + 1023) / 1024)     // 98 scan chunks

// ---------------- scratch (static device globals; no allocation) -------------
__device__ float g_dis[NN];
__device__ float g_selfnorm[NN];
__device__ float g_h1[(size_t)NN * HID];
__device__ float g_agg1[(size_t)NN * HID];
__device__ float g_h2[(size_t)NN * NCLS];
__device__ int   g_count[NN];
__device__ int   g_off[NN];
__device__ int   g_cursor[NN];
__device__ int   g_bsum[128];
__device__ int   g_bcarry[128];
__device__ int2  g_edge[EE];             // (src, w-bits) sorted by dst
__device__ __nv_bfloat16 g_w1t_hi[HID * INDIM];
__device__ __nv_bfloat16 g_w1t_lo[HID * INDIM];

// ---------------- helpers -----------------------------------------------------
__device__ __forceinline__ uint32_t packbf(float first, float second) {
    uint32_t r;
    asm("cvt.rn.bf16x2.f32 %0, %1, %2;" : "=r"(r) : "f"(second), "f"(first));
    return r;
}

__device__ __forceinline__ void mma_bf16(float& d0, float& d1, float& d2, float& d3,
                                         uint32_t a0, uint32_t a1, uint32_t a2, uint32_t a3,
                                         uint32_t b0, uint32_t b1) {
    asm volatile(
        "mma.sync.aligned.m16n8k16.row.col.f32.bf16.bf16.f32 "
        "{%0,%1,%2,%3}, {%4,%5,%6,%7}, {%8,%9}, {%0,%1,%2,%3};"
        : "+f"(d0), "+f"(d1), "+f"(d2), "+f"(d3)
        : "r"(a0), "r"(a1), "r"(a2), "r"(a3), "r"(b0), "r"(b1));
}

// ---------------- CSR build ---------------------------------------------------
__global__ void k_zero() {
    int i = blockIdx.x * blockDim.x + threadIdx.x;
    if (i < NN) g_count[i] = 0;
}

__global__ void k_hist(const int* __restrict__ dst) {
    int e = blockIdx.x * blockDim.x + threadIdx.x;
    if (e < EE) atomicAdd(&g_count[dst[e]], 1);
}

__global__ void k_scan1() {
    __shared__ int sm[1024];
    int tid = threadIdx.x;
    int i = blockIdx.x * 1024 + tid;
    int v = (i < NN) ? g_count[i] : 0;
    sm[tid] = v;
    __syncthreads();
#pragma unroll
    for (int off = 1; off < 1024; off <<= 1) {
        int t = (tid >= off) ? sm[tid - off] : 0;
        __syncthreads();
        sm[tid] += t;
        __syncthreads();
    }
    if (i < NN) g_off[i] = sm[tid] - v;
    if (tid == 1023) g_bsum[blockIdx.x] = sm[tid];
}

__global__ void k_scan2() {
    __shared__ int sm[128];
    int tid = threadIdx.x;
    int v = (tid < NCH) ? g_bsum[tid] : 0;
    sm[tid] = v;
    __syncthreads();
#pragma unroll
    for (int off = 1; off < 128; off <<= 1) {
        int t = (tid >= off) ? sm[tid - off] : 0;
        __syncthreads();
        sm[tid] += t;
        __syncthreads();
    }
    g_bcarry[tid] = sm[tid] - v;
}

__global__ void k_scan3() {
    int i = blockIdx.x * blockDim.x + threadIdx.x;
    if (i < NN) {
        int o = g_off[i] + g_bcarry[i >> 10];
        g_off[i] = o;
        g_cursor[i] = o;
    }
}

__global__ void k_fill(const int* __restrict__ src, const int* __restrict__ dst,
                       const float* __restrict__ ew) {
    int e = blockIdx.x * blockDim.x + threadIdx.x;
    if (e >= EE) return;
    int d = dst[e];
    int pos = atomicAdd(&g_cursor[d], 1);
    g_edge[pos] = make_int2(src[e], __float_as_int(ew[e]));
}

// warp per dst: deg = 1 + sum(w); dis = rsqrt(deg); selfnorm = dis^2
__global__ void k_deg_csr() {
    int d = blockIdx.x * 8 + (threadIdx.x >> 5);
    if (d >= NN) return;
    int lane = threadIdx.x & 31;
    int start = g_off[d], n = g_count[d];
    float s = 0.f;
    for (int j = lane; j < n; j += 32) s += __int_as_float(g_edge[start + j].y);
#pragma unroll
    for (int m = 16; m; m >>= 1) s += __shfl_xor_sync(0xFFFFFFFFu, s, m);
    if (lane == 0) {
        float r = rsqrtf(s + 1.0f);
        g_dis[d] = r;
        g_selfnorm[d] = r * r;
    }
}

// fold dis[src] into stored edge weight: edge.y = w * dis[src]
__global__ void k_prenorm() {
    int j = blockIdx.x * blockDim.x + threadIdx.x;
    if (j >= EE) return;
    int2 ed = g_edge[j];
    g_edge[j].y = __float_as_int(__int_as_float(ed.y) * g_dis[ed.x]);
}

// ---------------- W1^T split prep ---------------------------------------------
__global__ void k_prep_w(const float* __restrict__ W1) {
    int idx = blockIdx.x * blockDim.x + threadIdx.x;
    if (idx >= HID * INDIM) return;
    int n = idx >> 9;
    int k = idx & 511;
    float w = W1[k * HID + n];
    __nv_bfloat16 h = __float2bfloat16_rn(w);
    float hf = __bfloat162float(h);
    g_w1t_hi[n * INDIM + k] = h;
    g_w1t_lo[n * INDIM + k] = __float2bfloat16_rn(w - hf);
}

// ---------------- GEMM1 via mma.sync split-bf16 (h1 only) ---------------------
#define KC     32
#define APITCH 40
#define APB    (APITCH * 2)

__global__ void __launch_bounds__(256)
k_gemm1_tc(const float* __restrict__ x) {
    __shared__ uint8_t As_hi[128 * APB];
    __shared__ uint8_t As_lo[128 * APB];
    __shared__ uint8_t Bs_hi[64 * APB];
    __shared__ uint8_t Bs_lo[64 * APB];

    int tid = threadIdx.x;
    int wid = tid >> 5;
    int lane = tid & 31;
    int lt = lane >> 2;
    int q  = lane & 3;
    int row0 = blockIdx.x * 128;

    float acc[8][4];
#pragma unroll
    for (int t = 0; t < 8; t++)
#pragma unroll
        for (int j = 0; j < 4; j++) acc[t][j] = 0.0f;

    const uint2* whi = reinterpret_cast<const uint2*>(g_w1t_hi);
    const uint2* wlo = reinterpret_cast<const uint2*>(g_w1t_lo);

    for (int k0 = 0; k0 < INDIM; k0 += KC) {
#pragma unroll
        for (int i = 0; i < 4; i++) {
            int idx = tid + i * 256;
            int r = idx >> 3;
            int c4 = (idx & 7) * 4;
            float4 v = make_float4(0.f, 0.f, 0.f, 0.f);
            int grow = row0 + r;
            if (grow < NN)
                v = *reinterpret_cast<const float4*>(&x[(size_t)grow * INDIM + k0 + c4]);
            uint32_t hp0 = packbf(v.x, v.y);
            uint32_t hp1 = packbf(v.z, v.w);
            float hx = __uint_as_float(hp0 << 16);
            float hy = __uint_as_float(hp0 & 0xFFFF0000u);
            float hz = __uint_as_float(hp1 << 16);
            float hw = __uint_as_float(hp1 & 0xFFFF0000u);
            uint32_t lp0 = packbf(v.x - hx, v.y - hy);
            uint32_t lp1 = packbf(v.z - hz, v.w - hw);
            uint32_t off = (uint32_t)(r * APB + c4 * 2);
            *reinterpret_cast<uint2*>(As_hi + off) = make_uint2(hp0, hp1);
            *reinterpret_cast<uint2*>(As_lo + off) = make_uint2(lp0, lp1);
        }
#pragma unroll
        for (int i = 0; i < 2; i++) {
            int idx = tid + i * 256;
            int n = idx >> 3;
            int j = idx & 7;
            int gidx = n * 128 + (k0 >> 2) + j;
            uint32_t off = (uint32_t)(n * APB + j * 8);
            *reinterpret_cast<uint2*>(Bs_hi + off) = whi[gidx];
            *reinterpret_cast<uint2*>(Bs_lo + off) = wlo[gidx];
        }
        __syncthreads();

#pragma unroll
        for (int ks = 0; ks < 2; ks++) {
            uint32_t abase = (uint32_t)((wid * 16 + lt) * APB + ks * 32 + q * 4);
            uint32_t ah0 = *reinterpret_cast<const uint32_t*>(As_hi + abase);
            uint32_t ah1 = *reinterpret_cast<const uint32_t*>(As_hi + abase + 8 * APB);
            uint32_t ah2 = *reinterpret_cast<const uint32_t*>(As_hi + abase + 16);
            uint32_t ah3 = *reinterpret_cast<const uint32_t*>(As_hi + abase + 8 * APB + 16);
            uint32_t al0 = *reinterpret_cast<const uint32_t*>(As_lo + abase);
            uint32_t al1 = *reinterpret_cast<const uint32_t*>(As_lo + abase + 8 * APB);
            uint32_t al2 = *reinterpret_cast<const uint32_t*>(As_lo + abase + 16);
            uint32_t al3 = *reinterpret_cast<const uint32_t*>(As_lo + abase + 8 * APB + 16);
#pragma unroll
            for (int nt = 0; nt < 8; nt++) {
                uint32_t bbase = (uint32_t)((nt * 8 + lt) * APB + ks * 32 + q * 4);
                uint32_t bh0 = *reinterpret_cast<const uint32_t*>(Bs_hi + bbase);
                uint32_t bh1 = *reinterpret_cast<const uint32_t*>(Bs_hi + bbase + 16);
                uint32_t bl0 = *reinterpret_cast<const uint32_t*>(Bs_lo + bbase);
                uint32_t bl1 = *reinterpret_cast<const uint32_t*>(Bs_lo + bbase + 16);
                mma_bf16(acc[nt][0], acc[nt][1], acc[nt][2], acc[nt][3],
                         ah0, ah1, ah2, ah3, bh0, bh1);
                mma_bf16(acc[nt][0], acc[nt][1], acc[nt][2], acc[nt][3],
                         ah0, ah1, ah2, ah3, bl0, bl1);
                mma_bf16(acc[nt][0], acc[nt][1], acc[nt][2], acc[nt][3],
                         al0, al1, al2, al3, bh0, bh1);
            }
        }
        __syncthreads();
    }

    int rA = row0 + wid * 16 + lt;
    int rB = rA + 8;
#pragma unroll
    for (int nt = 0; nt < 8; nt++) {
        int col = nt * 8 + q * 2;
        if (rA < NN)
            *reinterpret_cast<float2*>(&g_h1[(size_t)rA * HID + col]) =
                make_float2(acc[nt][0], acc[nt][1]);
        if (rB < NN)
            *reinterpret_cast<float2*>(&g_h1[(size_t)rB * HID + col]) =
                make_float2(acc[nt][2], acc[nt][3]);
    }
}

// ---------------- layer-1 aggregation: warp per dst, gather-reduce ------------
__global__ void __launch_bounds__(256)
k_agg1() {
    int d = blockIdx.x * 8 + (threadIdx.x >> 5);
    if (d >= NN) return;
    int lane = threadIdx.x & 31;
    int start = g_off[d], n = g_count[d];
    float dd = g_dis[d];
    float sl = g_selfnorm[d];
    float2 acc = *reinterpret_cast<const float2*>(&g_h1[(size_t)d * HID + lane * 2]);
    acc.x *= sl; acc.y *= sl;
    const int2* ep = g_edge + start;
    for (int j = 0; j < n; j++) {
        int2 ed = ep[j];
        float nm = __int_as_float(ed.y) * dd;
        float2 v = *reinterpret_cast<const float2*>(&g_h1[(size_t)ed.x * HID + lane * 2]);
        acc.x = fmaf(v.x, nm, acc.x);
        acc.y = fmaf(v.y, nm, acc.y);
    }
    *reinterpret_cast<float2*>(&g_agg1[(size_t)d * HID + lane * 2]) = acc;
}

// ---------------- GEMM2: relu(agg1+b1) @ W2 -> h2 ----------------------------
__global__ void k_gemm2(const float* __restrict__ b1, const float* __restrict__ W2) {
    __shared__ float w2s[HID * NCLS];
    __shared__ float b1s[HID];
    int tid = threadIdx.x;
    for (int i = tid; i < HID * NCLS; i += blockDim.x) w2s[i] = W2[i];
    if (tid < HID) b1s[tid] = b1[tid];
    __syncthreads();
    int row = blockIdx.x * blockDim.x + tid;
    if (row >= NN) return;
    float acc[NCLS];
#pragma unroll
    for (int c = 0; c < NCLS; c++) acc[c] = 0.0f;
    const float4* arow = reinterpret_cast<const float4*>(&g_agg1[(size_t)row * HID]);
#pragma unroll
    for (int k4 = 0; k4 < HID / 4; k4++) {
        float4 v = arow[k4];
        float z0 = fmaxf(v.x + b1s[4 * k4 + 0], 0.0f);
        float z1 = fmaxf(v.y + b1s[4 * k4 + 1], 0.0f);
        float z2 = fmaxf(v.z + b1s[4 * k4 + 2], 0.0f);
        float z3 = fmaxf(v.w + b1s[4 * k4 + 3], 0.0f);
#pragma unroll
        for (int c = 0; c < NCLS; c++) {
            acc[c] = fmaf(z0, w2s[(4 * k4 + 0) * NCLS + c], acc[c]);
            acc[c] = fmaf(z1, w2s[(4 * k4 + 1) * NCLS + c], acc[c]);
            acc[c] = fmaf(z2, w2s[(4 * k4 + 2) * NCLS + c], acc[c]);
            acc[c] = fmaf(z3, w2s[(4 * k4 + 3) * NCLS + c], acc[c]);
        }
    }
#pragma unroll
    for (int c = 0; c < NCLS; c++) g_h2[(size_t)row * NCLS + c] = acc[c];
}

// ---------------- layer-2 aggregation + bias + log_softmax (fused) ------------
// 2 dsts per warp (16 lanes each); shfl-bfly softmax within 16-lane group
__global__ void __launch_bounds__(256)
k_agg2_sm(const float* __restrict__ b2, float* __restrict__ out) {
    int warp = blockIdx.x * 8 + (threadIdx.x >> 5);
    int lane = threadIdx.x & 31;
    int d = warp * 2 + (lane >> 4);
    int f = lane & 15;
    if (d >= NN) return;
    int start = g_off[d], n = g_count[d];
    float dd = g_dis[d];
    float acc = g_h2[(size_t)d * NCLS + f] * g_selfnorm[d];
    const int2* ep = g_edge + start;
    for (int j = 0; j < n; j++) {
        int2 ed = ep[j];
        float nm = __int_as_float(ed.y) * dd;
        acc = fmaf(g_h2[(size_t)ed.x * NCLS + f], nm, acc);
    }
    float v = acc + b2[f];
    float m = v;
#pragma unroll
    for (int msk = 8; msk; msk >>= 1) m = fmaxf(m, __shfl_xor_sync(0xFFFFFFFFu, m, msk));
    float s = expf(v - m);
#pragma unroll
    for (int msk = 8; msk; msk >>= 1) s += __shfl_xor_sync(0xFFFFFFFFu, s, msk);
    out[(size_t)d * NCLS + f] = v - (logf(s) + m);
}

// ---------------- launch ------------------------------------------------------
extern "C" void kernel_launch(void* const* d_in, const int* in_sizes, int n_in,
                              void* d_out, int out_size) {
    const float* x  = (const float*)d_in[0];
    const int*   ei = (const int*)  d_in[1];
    const float* ew = (const float*)d_in[2];
    const float* W1 = (const float*)d_in[3];
    const float* b1 = (const float*)d_in[4];
    const float* W2 = (const float*)d_in[5];
    const float* b2 = (const float*)d_in[6];
    float* out = (float*)d_out;

    const int* src = ei;
    const int* dst = ei + EE;

    k_zero     <<<(NN + 255) / 256, 256>>>();
    k_hist     <<<(EE + 255) / 256, 256>>>(dst);
    k_scan1    <<<NCH, 1024>>>();
    k_scan2    <<<1, 128>>>();
    k_scan3    <<<(NN + 255) / 256, 256>>>();
    k_fill     <<<(EE + 255) / 256, 256>>>(src, dst, ew);
    k_deg_csr  <<<(NN + 7) / 8, 256>>>();
    k_prenorm  <<<(EE + 255) / 256, 256>>>();
    k_prep_w   <<<(HID * INDIM + 255) / 256, 256>>>(W1);

    k_gemm1_tc <<<(NN + 127) / 128, 256>>>(x);
    k_agg1     <<<(NN + 7) / 8, 256>>>();
    k_gemm2    <<<(NN + 255) / 256, 256>>>(b1, W2);
    k_agg2_sm  <<<(NN / 2 + 7) / 8, 256>>>(b2, out);
}